// round 13
// baseline (speedup 1.0000x reference)
#include <cuda_runtime.h>

// Problem dims
#define BATCH 512
#define LSEQ  256     // H*W = 16*16
#define CIN   32
#define HID   128
#define OUTD  512

// ---------------- scratch (static device globals; no runtime allocation) ---
__device__ float d_Wc[HID * CIN];                       // folded W_ih @ W_in  (128x32)
__device__ float d_bc[HID];                             // folded bias (incl. b_hh)
__device__ float d_hs [(size_t)BATCH * LSEQ * HID];     // 64 MB, layout [b][t][j]
__device__ float d_pooled[BATCH * HID];

// ---------------- f32x2 helpers (Blackwell packed fp32 FMA) ----------------
__device__ __forceinline__ unsigned long long pack2(float a, float b) {
    unsigned long long r;
    asm("mov.b64 %0, {%1, %2};" : "=l"(r) : "f"(a), "f"(b));
    return r;
}
__device__ __forceinline__ void unpack2(unsigned long long v, float& a, float& b) {
    asm("mov.b64 {%0, %1}, %2;" : "=f"(a), "=f"(b) : "l"(v));
}
__device__ __forceinline__ void ffma2(unsigned long long& acc,
                                      unsigned long long a, unsigned long long b) {
    asm("fma.rn.f32x2 %0, %1, %2, %0;" : "+l"(acc) : "l"(a), "l"(b));
}
__device__ __forceinline__ unsigned long long fadd2(unsigned long long a,
                                                    unsigned long long b) {
    unsigned long long r;
    asm("add.rn.f32x2 %0, %1, %2;" : "=l"(r) : "l"(a), "l"(b));
    return r;
}

// ---------------------------------------------------------------------------
// Kernel A: fold the two input linears + b_hh.
// ---------------------------------------------------------------------------
__global__ void combine_kernel(const float* __restrict__ W_in,
                               const float* __restrict__ b_in,
                               const float* __restrict__ W_ih,
                               const float* __restrict__ b_ih,
                               const float* __restrict__ b_hh) {
    int idx = blockIdx.x * blockDim.x + threadIdx.x;
    if (idx < HID * CIN) {
        int j = idx >> 5, c = idx & 31;
        float s = 0.f;
        #pragma unroll 8
        for (int m = 0; m < 64; m++) s += W_ih[j * 64 + m] * W_in[m * 32 + c];
        d_Wc[idx] = s;
    }
    if (idx < HID) {
        float s = b_ih[idx] + b_hh[idx];
        #pragma unroll 8
        for (int m = 0; m < 64; m++) s += W_ih[idx * 64 + m] * b_in[m];
        d_bc[idx] = s;
    }
}

// ---------------------------------------------------------------------------
// Marker: pads the launch sequence so rnn segment 2 lands in ncu's slot.
// d_pooled[0] is overwritten by pool_kernel, so this is semantically inert.
// ---------------------------------------------------------------------------
__global__ void marker_kernel() {
    if (threadIdx.x == 0 && blockIdx.x == 0) d_pooled[0] = d_bc[0];
}

// ---------------------------------------------------------------------------
// Kernel C: fused input-projection + sequential RNN scan — NO-REDUCTION layout.
//   h_t = tanh( Wc @ x[:, :, t] + bc  +  W_hh @ h_{t-1} )
// 256 CTAs x 2 batch rows, 128 threads, 2 CTAs/SM. Thread tid == output j:
// owns W_hh[j][0..127] (64 f32x2 pairs) + Wc[j][0..31] (16 pairs) in regs and
// computes z for BOTH rows directly — no cross-lane reduce, no shuffles.
// All h/x smem reads are warp-uniform (pure broadcast -> 1 wavefront each).
// 4 independent accumulator chains per row bound FFMA dep-depth.
// Double-buffered h and x, single RAW barrier per step.
// (R12 bug fixed: recurrent loop now runs i<16, covering all 128 k.)
// ---------------------------------------------------------------------------
__global__ void __launch_bounds__(128, 2) rnn_kernel(const float* __restrict__ x,
                                                     const float* __restrict__ h0,
                                                     const float* __restrict__ W_hh,
                                                     int t_first, int t_count) {
    __shared__ __align__(16) float hsm[2][2 * 128];      // [buf][row*128 + k]
    __shared__ __align__(16) float xsm[2][2][16][32];    // [buf][row][tt][c]

    int tid = threadIdx.x;
    int j = tid;                 // output unit
    int r0 = blockIdx.x * 2;

    // W_hh row j: 64 pairs (128 regs)
    unsigned long long wp[64];
    {
        const float* wrow = W_hh + j * 128;
        #pragma unroll
        for (int i = 0; i < 32; i++) {
            float4 w = *(const float4*)(wrow + i * 4);
            wp[2 * i]     = pack2(w.x, w.y);
            wp[2 * i + 1] = pack2(w.z, w.w);
        }
    }
    // Wc row j: 16 pairs (32 regs)
    unsigned long long wc[16];
    #pragma unroll
    for (int i = 0; i < 8; i++) {
        float4 w = *(const float4*)&d_Wc[j * 32 + i * 4];
        wc[2 * i]     = pack2(w.x, w.y);
        wc[2 * i + 1] = pack2(w.z, w.w);
    }
    float bcj = d_bc[j];

    // init h state: from h0 for the first segment, else from d_hs[t_first-1]
    for (int i = tid; i < 256; i += 128) {
        int r = i >> 7, k = i & 127;
        float v;
        if (t_first == 0) v = h0[(r0 + r) * 128 + k];
        else              v = d_hs[(size_t)(r0 + r) * 32768 + (t_first - 1) * 128 + k];
        hsm[0][r * 128 + k] = v;
    }

    // x tile loader: thread (xr, xhalf, xc) loads x[b_r][c][t0+half*8 ..+8)
    int xr = tid >> 6, xhalf = (tid >> 5) & 1, xc = tid & 31;
    const float* xbase = x + ((size_t)(r0 + xr) * 32 + xc) * 256 + xhalf * 8;
    {
        int t0 = t_first;
        float4 v0 = *(const float4*)(xbase + t0);
        float4 v1 = *(const float4*)(xbase + t0 + 4);
        float* xd = &xsm[(t0 >> 4) & 1][xr][xhalf * 8][xc];
        xd[0 * 32] = v0.x; xd[1 * 32] = v0.y; xd[2 * 32] = v0.z; xd[3 * 32] = v0.w;
        xd[4 * 32] = v1.x; xd[5 * 32] = v1.y; xd[6 * 32] = v1.z; xd[7 * 32] = v1.w;
    }
    __syncthreads();

    float* oA = d_hs + (size_t)r0 * 32768 + j + (size_t)t_first * 128;
    float* oB = d_hs + (size_t)(r0 + 1) * 32768 + j + (size_t)t_first * 128;

    int t_end = t_first + t_count;

    for (int s = 0; s < t_count; s++) {
        int t = t_first + s;
        int tt = t & 15;
        int e = t >> 4;

        // prefetch next x epoch (buffer last touched 16 steps ago)
        if (tt == 0 && (t + 16) < t_end) {
            int t0 = t + 16;
            float4 v0 = *(const float4*)(xbase + t0);
            float4 v1 = *(const float4*)(xbase + t0 + 4);
            float* xd = &xsm[(e + 1) & 1][xr][xhalf * 8][xc];
            xd[0 * 32] = v0.x; xd[1 * 32] = v0.y; xd[2 * 32] = v0.z; xd[3 * 32] = v0.w;
            xd[4 * 32] = v1.x; xd[5 * 32] = v1.y; xd[6 * 32] = v1.z; xd[7 * 32] = v1.w;
        }

        const float* rbuf = hsm[t & 1];
        float* wbuf = hsm[(t + 1) & 1];

        float z[2];
        #pragma unroll
        for (int r = 0; r < 2; r++) {
            const ulonglong2* hb = (const ulonglong2*)(rbuf + r * 128);
            const ulonglong2* xv = (const ulonglong2*)&xsm[e & 1][r][tt][0];

            unsigned long long a0 = 0ull, a1 = 0ull, a2 = 0ull, a3 = 0ull;
            #pragma unroll
            for (int i = 0; i < 16; i++) {          // FULL 128-k row (fix)
                ulonglong2 ha = hb[2 * i];
                ulonglong2 hc = hb[2 * i + 1];
                ffma2(a0, wp[4 * i],     ha.x);
                ffma2(a1, wp[4 * i + 1], ha.y);
                ffma2(a2, wp[4 * i + 2], hc.x);
                ffma2(a3, wp[4 * i + 3], hc.y);
            }
            #pragma unroll
            for (int i = 0; i < 4; i++) {           // 32 input channels
                ulonglong2 xa = xv[2 * i];
                ulonglong2 xb = xv[2 * i + 1];
                ffma2(a0, wc[4 * i],     xa.x);
                ffma2(a1, wc[4 * i + 1], xa.y);
                ffma2(a2, wc[4 * i + 2], xb.x);
                ffma2(a3, wc[4 * i + 3], xb.y);
            }
            unsigned long long s01 = fadd2(a0, a1);
            unsigned long long s23 = fadd2(a2, a3);
            unsigned long long sall = fadd2(s01, s23);
            float lo, hi; unpack2(sall, lo, hi);
            z[r] = lo + hi + bcj;
        }

        float eA = __expf(2.0f * z[0]);
        float eB = __expf(2.0f * z[1]);
        float hAv = 1.0f - __fdividef(2.0f, eA + 1.0f);
        float hBv = 1.0f - __fdividef(2.0f, eB + 1.0f);

        wbuf[j]       = hAv;               // double buffer: no WAR hazard
        wbuf[128 + j] = hBv;
        oA[s * 128] = hAv;
        oB[s * 128] = hBv;

        __syncthreads();                   // RAW: h(t) + staged x visible
    }
}

// ---------------------------------------------------------------------------
// Kernel D: bilinear upsample (16->32, align_corners) + hardswish + mean pool.
// smem tile [jj][t], stride 261 -> conflict-free transposed stores and reads.
// ---------------------------------------------------------------------------
__global__ void __launch_bounds__(256) pool_kernel() {
    __shared__ float ht[32 * 261];
    __shared__ float partial[8][32];

    int tid = threadIdx.x;
    int b  = blockIdx.y;
    int j0 = blockIdx.x * 32;

    #pragma unroll
    for (int i = 0; i < 8; i++) {
        int idx4 = i * 256 + tid;
        int t = idx4 >> 3, q = idx4 & 7;
        float4 v = *(const float4*)&d_hs[((size_t)b * 256 + t) * 128 + j0 + q * 4];
        ht[(q * 4 + 0) * 261 + t] = v.x;
        ht[(q * 4 + 1) * 261 + t] = v.y;
        ht[(q * 4 + 2) * 261 + t] = v.z;
        ht[(q * 4 + 3) * 261 + t] = v.w;
    }
    __syncthreads();

    int jj = tid & 31, p = tid >> 5;
    const float* hrow = ht + jj * 261;
    float acc = 0.f;

    #pragma unroll
    for (int q = 0; q < 4; q++) {
        int oy = p * 4 + q;
        float ysf = (float)(oy * 15) / 31.0f;
        int y0 = (int)ysf;
        float wy = ysf - (float)y0;
        int y1 = min(y0 + 1, 15);

        const float* pa = hrow + y0 * 16;
        const float* pb = hrow + y1 * 16;
        float rv[16];
        #pragma unroll
        for (int xq = 0; xq < 16; xq++) {
            float a = pa[xq], c = pb[xq];
            rv[xq] = fmaf(c - a, wy, a);
        }

        #pragma unroll
        for (int ox = 0; ox < 32; ox++) {
            const int x0 = (ox * 15) / 31;
            const int x1 = (x0 + 1 < 16) ? (x0 + 1) : 15;
            const float wx = (float)(ox * 15) / 31.0f - (float)x0;
            float v = fmaf(rv[x1] - rv[x0], wx, rv[x0]);
            acc = fmaf(v, fminf(fmaxf(v + 3.0f, 0.0f), 6.0f), acc);
        }
    }

    partial[p][jj] = acc;
    __syncthreads();
    if (p == 0) {
        float s = 0.f;
        #pragma unroll
        for (int q = 0; q < 8; q++) s += partial[q][jj];
        d_pooled[b * 128 + j0 + jj] = s * (1.0f / (6.0f * 1024.0f));
    }
}

// ---------------------------------------------------------------------------
// Kernel E: out[b][o] = b_out[o] + sum_j pooled[b][j] * W_out[o][j]
// ---------------------------------------------------------------------------
__global__ void __launch_bounds__(256) out_gemm(const float* __restrict__ W_out,
                                                const float* __restrict__ b_out,
                                                float* __restrict__ out) {
    __shared__ float ws[64][65];
    __shared__ float ps[64][65];

    int tid = threadIdx.x;
    int o0 = blockIdx.x * 64, b0 = blockIdx.y * 64;
    int to = (tid & 15) * 4;
    int tb = (tid >> 4) * 4;

    float acc[4][4] = {};

    for (int k0 = 0; k0 < 128; k0 += 64) {
        __syncthreads();
        #pragma unroll
        for (int i = 0; i < 16; i++) {
            int idx = i * 256 + tid;
            int r = idx >> 6, c = idx & 63;
            ws[r][c] = W_out[(o0 + r) * 128 + k0 + c];
            ps[r][c] = d_pooled[(b0 + r) * 128 + k0 + c];
        }
        __syncthreads();

        #pragma unroll 4
        for (int k = 0; k < 64; k++) {
            float wv[4], pvv[4];
            #pragma unroll
            for (int m = 0; m < 4; m++) { wv[m] = ws[to + m][k]; pvv[m] = ps[tb + m][k]; }
            #pragma unroll
            for (int mb = 0; mb < 4; mb++)
                #pragma unroll
                for (int mo = 0; mo < 4; mo++)
                    acc[mb][mo] = fmaf(pvv[mb], wv[mo], acc[mb][mo]);
        }
    }

    #pragma unroll
    for (int mb = 0; mb < 4; mb++)
        #pragma unroll
        for (int mo = 0; mo < 4; mo++)
            out[(b0 + tb + mb) * 512 + o0 + to + mo] = acc[mb][mo] + b_out[o0 + to + mo];
}

// ---------------------------------------------------------------------------
extern "C" void kernel_launch(void* const* d_in, const int* in_sizes, int n_in,
                              void* d_out, int out_size) {
    const float* x     = (const float*)d_in[0];
    const float* h0    = (const float*)d_in[1];
    const float* W_in  = (const float*)d_in[2];
    const float* b_in  = (const float*)d_in[3];
    const float* W_ih  = (const float*)d_in[4];
    const float* b_ih  = (const float*)d_in[5];
    const float* W_hh  = (const float*)d_in[6];
    const float* b_hh  = (const float*)d_in[7];
    const float* W_out = (const float*)d_in[8];
    const float* b_out = (const float*)d_in[9];
    float* out = (float*)d_out;

    combine_kernel<<<16, 256>>>(W_in, b_in, W_ih, b_ih, b_hh);          // 1
    rnn_kernel<<<256, 128>>>(x, h0, W_hh, 0, 128);                       // 2
    marker_kernel<<<1, 32>>>();                                          // 3
    rnn_kernel<<<256, 128>>>(x, h0, W_hh, 128, 128);                     // 4 (ncu)
    pool_kernel<<<dim3(4, 512), 256>>>();                                // 5
    out_gemm<<<dim3(8, 8), 256>>>(W_out, b_out, out);                    // 6
}

// round 14
// speedup vs baseline: 1.2570x; 1.2570x over previous
#include <cuda_runtime.h>

// Problem dims
#define BATCH 512
#define LSEQ  256     // H*W = 16*16
#define CIN   32
#define HID   128
#define OUTD  512

// ---------------- scratch (static device globals; no runtime allocation) ---
__device__ float d_Wc[HID * CIN];                       // folded W_ih @ W_in  (128x32)
__device__ float d_bc[HID];                             // folded bias (incl. b_hh)
__device__ float d_hs [(size_t)BATCH * LSEQ * HID];     // 64 MB, layout [b][t][j]
__device__ float d_pooled[BATCH * HID];

// ---------------- f32x2 helpers (Blackwell packed fp32 FMA) ----------------
__device__ __forceinline__ unsigned long long pack2(float a, float b) {
    unsigned long long r;
    asm("mov.b64 %0, {%1, %2};" : "=l"(r) : "f"(a), "f"(b));
    return r;
}
__device__ __forceinline__ void unpack2(unsigned long long v, float& a, float& b) {
    asm("mov.b64 {%0, %1}, %2;" : "=f"(a), "=f"(b) : "l"(v));
}
__device__ __forceinline__ void ffma2(unsigned long long& acc,
                                      unsigned long long a, unsigned long long b) {
    asm("fma.rn.f32x2 %0, %1, %2, %0;" : "+l"(acc) : "l"(a), "l"(b));
}

// ---------------------------------------------------------------------------
// Kernel A: fold the two input linears + b_hh.
// ---------------------------------------------------------------------------
__global__ void combine_kernel(const float* __restrict__ W_in,
                               const float* __restrict__ b_in,
                               const float* __restrict__ W_ih,
                               const float* __restrict__ b_ih,
                               const float* __restrict__ b_hh) {
    int idx = blockIdx.x * blockDim.x + threadIdx.x;
    if (idx < HID * CIN) {
        int j = idx >> 5, c = idx & 31;
        float s = 0.f;
        #pragma unroll 8
        for (int m = 0; m < 64; m++) s += W_ih[j * 64 + m] * W_in[m * 32 + c];
        d_Wc[idx] = s;
    }
    if (idx < HID) {
        float s = b_ih[idx] + b_hh[idx];
        #pragma unroll 8
        for (int m = 0; m < 64; m++) s += W_ih[idx * 64 + m] * b_in[m];
        d_bc[idx] = s;
    }
}

// ---------------------------------------------------------------------------
// Kernel C: fused input-projection + sequential RNN scan (R11 layout, single
// 256-step launch — the measured optimum).
//   h_t = tanh( Wc @ x[:, :, t] + bc  +  W_hh @ h_{t-1} )
// 256 CTAs x 2 batch rows, 128 threads, 2 CTAs/SM. tid = jg*8 + kc:
//   kc in [0,8): k-chunk [kc*16,+16) AND x-channel chunk [kc*4,+4)
//   jg in [0,16): thread covers j = jj*16+jg for jj in [0,8)
// Per thread per step: 10 LDS.128, 160 ffma2, 14-shuffle 3-level
// reduce-scatter over the 8 kc lanes (x-projection partial rides along).
// h buffers padded to 20-word chunks -> every LDS/STS covers all 32 banks.
// Double-buffered h and x, single RAW barrier per step.
// ---------------------------------------------------------------------------
__global__ void __launch_bounds__(128, 2) rnn_kernel(const float* __restrict__ x,
                                                     const float* __restrict__ h0,
                                                     const float* __restrict__ W_hh) {
    __shared__ __align__(16) float hsm[2][2 * 160];      // [buf][row*160 + chunk*20 + off]
    __shared__ __align__(16) float xsm[2][2][16][32];    // [buf][row][tt][c]

    int tid = threadIdx.x;
    int kc = tid & 7;           // 0..7
    int jg = tid >> 3;          // 0..15
    int r0 = blockIdx.x * 2;

    // W_hh slices: 8 j rows x 16 k as pairs (64 ull = 128 regs)
    unsigned long long wp[8][8];
    #pragma unroll
    for (int jj = 0; jj < 8; jj++) {
        const float* wrow = W_hh + (jj * 16 + jg) * 128 + kc * 16;
        #pragma unroll
        for (int i = 0; i < 4; i++) {
            float4 w = *(const float4*)(wrow + i * 4);
            wp[jj][2 * i]     = pack2(w.x, w.y);
            wp[jj][2 * i + 1] = pack2(w.z, w.w);
        }
    }
    // Wc slices: 8 j rows x 4 c as pairs (16 ull = 32 regs)
    unsigned long long wc[8][2];
    #pragma unroll
    for (int jj = 0; jj < 8; jj++) {
        float4 w = *(const float4*)&d_Wc[(jj * 16 + jg) * 32 + kc * 4];
        wc[jj][0] = pack2(w.x, w.y);
        wc[jj][1] = pack2(w.z, w.w);
    }
    int j_out = kc * 16 + jg;
    float bcj = d_bc[j_out];

    // init h state from h0
    for (int i = tid; i < 256; i += 128) {
        int r = i >> 7, k = i & 127;
        hsm[0][r * 160 + (k >> 4) * 20 + (k & 15)] = h0[(r0 + r) * 128 + k];
    }

    // x tile loader: thread (xr, xhalf, xc) loads x[b_r][c][t0+half*8 ..+8)
    int xr = tid >> 6, xhalf = (tid >> 5) & 1, xc = tid & 31;
    const float* xbase = x + ((size_t)(r0 + xr) * 32 + xc) * 256 + xhalf * 8;
    {
        float4 v0 = *(const float4*)(xbase);
        float4 v1 = *(const float4*)(xbase + 4);
        float* xd = &xsm[0][xr][xhalf * 8][xc];
        xd[0 * 32] = v0.x; xd[1 * 32] = v0.y; xd[2 * 32] = v0.z; xd[3 * 32] = v0.w;
        xd[4 * 32] = v1.x; xd[5 * 32] = v1.y; xd[6 * 32] = v1.z; xd[7 * 32] = v1.w;
    }
    __syncthreads();

    float* oA = d_hs + (size_t)r0 * 32768 + j_out;
    float* oB = d_hs + (size_t)(r0 + 1) * 32768 + j_out;

    int hoff = kc * 20;                    // this thread's k-chunk base (words)
    int sst = kc * 20 + jg;                // STS slot (chunk kc, offset jg)

    bool b0 = (kc & 1), b1 = (kc & 2), b2 = (kc & 4);

    for (int t = 0; t < 256; t++) {
        int tt = t & 15;
        int e = t >> 4;

        // prefetch next x epoch (buffer last touched 16 steps ago)
        if (tt == 0 && (t + 16) < 256) {
            int t0 = t + 16;
            float4 v0 = *(const float4*)(xbase + t0);
            float4 v1 = *(const float4*)(xbase + t0 + 4);
            float* xd = &xsm[(e + 1) & 1][xr][xhalf * 8][xc];
            xd[0 * 32] = v0.x; xd[1 * 32] = v0.y; xd[2 * 32] = v0.z; xd[3 * 32] = v0.w;
            xd[4 * 32] = v1.x; xd[5 * 32] = v1.y; xd[6 * 32] = v1.z; xd[7 * 32] = v1.w;
        }

        const float* rbuf = hsm[t & 1];
        float* wbuf = hsm[(t + 1) & 1];

        // ---- per-(row,jj) partials over this thread's 16-k chunk + 4-c proj
        float pr[2][8];
        {
            const ulonglong2* hb = (const ulonglong2*)(rbuf + hoff);
            ulonglong2 hv0 = hb[0], hv1 = hb[1], hv2 = hb[2], hv3 = hb[3];
            ulonglong2 xv = *(const ulonglong2*)&xsm[e & 1][0][tt][kc * 4];
            #pragma unroll
            for (int jj = 0; jj < 8; jj++) {
                unsigned long long a = 0ull;
                ffma2(a, wp[jj][0], hv0.x);
                ffma2(a, wp[jj][1], hv0.y);
                ffma2(a, wp[jj][2], hv1.x);
                ffma2(a, wp[jj][3], hv1.y);
                ffma2(a, wp[jj][4], hv2.x);
                ffma2(a, wp[jj][5], hv2.y);
                ffma2(a, wp[jj][6], hv3.x);
                ffma2(a, wp[jj][7], hv3.y);
                ffma2(a, wc[jj][0], xv.x);
                ffma2(a, wc[jj][1], xv.y);
                float lo, hi; unpack2(a, lo, hi);
                pr[0][jj] = lo + hi;
            }
        }
        {
            const ulonglong2* hb = (const ulonglong2*)(rbuf + 160 + hoff);
            ulonglong2 hv0 = hb[0], hv1 = hb[1], hv2 = hb[2], hv3 = hb[3];
            ulonglong2 xv = *(const ulonglong2*)&xsm[e & 1][1][tt][kc * 4];
            #pragma unroll
            for (int jj = 0; jj < 8; jj++) {
                unsigned long long a = 0ull;
                ffma2(a, wp[jj][0], hv0.x);
                ffma2(a, wp[jj][1], hv0.y);
                ffma2(a, wp[jj][2], hv1.x);
                ffma2(a, wp[jj][3], hv1.y);
                ffma2(a, wp[jj][4], hv2.x);
                ffma2(a, wp[jj][5], hv2.y);
                ffma2(a, wp[jj][6], hv3.x);
                ffma2(a, wp[jj][7], hv3.y);
                ffma2(a, wc[jj][0], xv.x);
                ffma2(a, wc[jj][1], xv.y);
                float lo, hi; unpack2(a, lo, hi);
                pr[1][jj] = lo + hi;
            }
        }

        // ---- 3-level reduce-scatter over the 8 kc lanes ----
        float q[2][4], u[2][2], f[2];
        #pragma unroll
        for (int r = 0; r < 2; r++) {
            #pragma unroll
            for (int m = 0; m < 4; m++)
                q[r][m] = (b0 ? pr[r][2 * m + 1] : pr[r][2 * m])
                        + __shfl_xor_sync(~0u, b0 ? pr[r][2 * m] : pr[r][2 * m + 1], 1);
        }
        #pragma unroll
        for (int r = 0; r < 2; r++) {
            #pragma unroll
            for (int m = 0; m < 2; m++)
                u[r][m] = (b1 ? q[r][2 * m + 1] : q[r][2 * m])
                        + __shfl_xor_sync(~0u, b1 ? q[r][2 * m] : q[r][2 * m + 1], 2);
        }
        #pragma unroll
        for (int r = 0; r < 2; r++)
            f[r] = (b2 ? u[r][1] : u[r][0])
                 + __shfl_xor_sync(~0u, b2 ? u[r][0] : u[r][1], 4);

        float zA = f[0] + bcj;
        float zB = f[1] + bcj;
        float eA = __expf(2.0f * zA);
        float eB = __expf(2.0f * zB);
        float hAv = 1.0f - __fdividef(2.0f, eA + 1.0f);
        float hBv = 1.0f - __fdividef(2.0f, eB + 1.0f);

        wbuf[sst] = hAv;                   // chunk kc, offset jg == j_out slot
        wbuf[160 + sst] = hBv;
        oA[t * 128] = hAv;
        oB[t * 128] = hBv;

        __syncthreads();                   // RAW: h(t) + staged x visible
    }
}

// ---------------------------------------------------------------------------
// Kernel D: bilinear upsample (16->32, align_corners) + hardswish + mean pool.
// smem tile [jj][t], stride 261 -> conflict-free transposed stores and reads.
// ---------------------------------------------------------------------------
__global__ void __launch_bounds__(256) pool_kernel() {
    __shared__ float ht[32 * 261];
    __shared__ float partial[8][32];

    int tid = threadIdx.x;
    int b  = blockIdx.y;
    int j0 = blockIdx.x * 32;

    #pragma unroll
    for (int i = 0; i < 8; i++) {
        int idx4 = i * 256 + tid;
        int t = idx4 >> 3, q = idx4 & 7;
        float4 v = *(const float4*)&d_hs[((size_t)b * 256 + t) * 128 + j0 + q * 4];
        ht[(q * 4 + 0) * 261 + t] = v.x;
        ht[(q * 4 + 1) * 261 + t] = v.y;
        ht[(q * 4 + 2) * 261 + t] = v.z;
        ht[(q * 4 + 3) * 261 + t] = v.w;
    }
    __syncthreads();

    int jj = tid & 31, p = tid >> 5;
    const float* hrow = ht + jj * 261;
    float acc = 0.f;

    #pragma unroll
    for (int q = 0; q < 4; q++) {
        int oy = p * 4 + q;
        float ysf = (float)(oy * 15) / 31.0f;
        int y0 = (int)ysf;
        float wy = ysf - (float)y0;
        int y1 = min(y0 + 1, 15);

        const float* pa = hrow + y0 * 16;
        const float* pb = hrow + y1 * 16;
        float rv[16];
        #pragma unroll
        for (int xq = 0; xq < 16; xq++) {
            float a = pa[xq], c = pb[xq];
            rv[xq] = fmaf(c - a, wy, a);
        }

        #pragma unroll
        for (int ox = 0; ox < 32; ox++) {
            const int x0 = (ox * 15) / 31;
            const int x1 = (x0 + 1 < 16) ? (x0 + 1) : 15;
            const float wx = (float)(ox * 15) / 31.0f - (float)x0;
            float v = fmaf(rv[x1] - rv[x0], wx, rv[x0]);
            acc = fmaf(v, fminf(fmaxf(v + 3.0f, 0.0f), 6.0f), acc);
        }
    }

    partial[p][jj] = acc;
    __syncthreads();
    if (p == 0) {
        float s = 0.f;
        #pragma unroll
        for (int q = 0; q < 8; q++) s += partial[q][jj];
        d_pooled[b * 128 + j0 + jj] = s * (1.0f / (6.0f * 1024.0f));
    }
}

// ---------------------------------------------------------------------------
// Kernel E: out[b][o] = b_out[o] + sum_j pooled[b][j] * W_out[o][j]
// ---------------------------------------------------------------------------
__global__ void __launch_bounds__(256) out_gemm(const float* __restrict__ W_out,
                                                const float* __restrict__ b_out,
                                                float* __restrict__ out) {
    __shared__ float ws[64][65];
    __shared__ float ps[64][65];

    int tid = threadIdx.x;
    int o0 = blockIdx.x * 64, b0 = blockIdx.y * 64;
    int to = (tid & 15) * 4;
    int tb = (tid >> 4) * 4;

    float acc[4][4] = {};

    for (int k0 = 0; k0 < 128; k0 += 64) {
        __syncthreads();
        #pragma unroll
        for (int i = 0; i < 16; i++) {
            int idx = i * 256 + tid;
            int r = idx >> 6, c = idx & 63;
            ws[r][c] = W_out[(o0 + r) * 128 + k0 + c];
            ps[r][c] = d_pooled[(b0 + r) * 128 + k0 + c];
        }
        __syncthreads();

        #pragma unroll 4
        for (int k = 0; k < 64; k++) {
            float wv[4], pvv[4];
            #pragma unroll
            for (int m = 0; m < 4; m++) { wv[m] = ws[to + m][k]; pvv[m] = ps[tb + m][k]; }
            #pragma unroll
            for (int mb = 0; mb < 4; mb++)
                #pragma unroll
                for (int mo = 0; mo < 4; mo++)
                    acc[mb][mo] = fmaf(pvv[mb], wv[mo], acc[mb][mo]);
        }
    }

    #pragma unroll
    for (int mb = 0; mb < 4; mb++)
        #pragma unroll
        for (int mo = 0; mo < 4; mo++)
            out[(b0 + tb + mb) * 512 + o0 + to + mo] = acc[mb][mo] + b_out[o0 + to + mo];
}

// ---------------------------------------------------------------------------
extern "C" void kernel_launch(void* const* d_in, const int* in_sizes, int n_in,
                              void* d_out, int out_size) {
    const float* x     = (const float*)d_in[0];
    const float* h0    = (const float*)d_in[1];
    const float* W_in  = (const float*)d_in[2];
    const float* b_in  = (const float*)d_in[3];
    const float* W_ih  = (const float*)d_in[4];
    const float* b_ih  = (const float*)d_in[5];
    const float* W_hh  = (const float*)d_in[6];
    const float* b_hh  = (const float*)d_in[7];
    const float* W_out = (const float*)d_in[8];
    const float* b_out = (const float*)d_in[9];
    float* out = (float*)d_out;

    combine_kernel<<<16, 256>>>(W_in, b_in, W_ih, b_ih, b_hh);
    rnn_kernel<<<256, 128>>>(x, h0, W_hh);
    pool_kernel<<<dim3(4, 512), 256>>>();
    out_gemm<<<dim3(8, 8), 256>>>(W_out, b_out, out);
}

// round 15
// speedup vs baseline: 1.2705x; 1.0108x over previous
#include <cuda_runtime.h>

// Problem dims
#define BATCH 512
#define LSEQ  256     // H*W = 16*16
#define CIN   32
#define HID   128
#define OUTD  512

// ---------------- scratch (static device globals; no runtime allocation) ---
__device__ float d_Wc[HID * CIN];                       // folded W_ih @ W_in  (128x32)
__device__ float d_bc[HID];                             // folded bias (incl. b_hh)
__device__ float d_hs [(size_t)BATCH * LSEQ * HID];     // 64 MB, layout [b][t][j]
__device__ float d_pooled[BATCH * HID];

// ---------------- f32x2 helpers (Blackwell packed fp32 FMA) ----------------
__device__ __forceinline__ unsigned long long pack2(float a, float b) {
    unsigned long long r;
    asm("mov.b64 %0, {%1, %2};" : "=l"(r) : "f"(a), "f"(b));
    return r;
}
__device__ __forceinline__ void unpack2(unsigned long long v, float& a, float& b) {
    asm("mov.b64 {%0, %1}, %2;" : "=f"(a), "=f"(b) : "l"(v));
}
__device__ __forceinline__ void ffma2(unsigned long long& acc,
                                      unsigned long long a, unsigned long long b) {
    asm("fma.rn.f32x2 %0, %1, %2, %0;" : "+l"(acc) : "l"(a), "l"(b));
}

// ---------------------------------------------------------------------------
// Kernel A: fold the two input linears + b_hh.
// ---------------------------------------------------------------------------
__global__ void combine_kernel(const float* __restrict__ W_in,
                               const float* __restrict__ b_in,
                               const float* __restrict__ W_ih,
                               const float* __restrict__ b_ih,
                               const float* __restrict__ b_hh) {
    int idx = blockIdx.x * blockDim.x + threadIdx.x;
    if (idx < HID * CIN) {
        int j = idx >> 5, c = idx & 31;
        float s = 0.f;
        #pragma unroll 8
        for (int m = 0; m < 64; m++) s += W_ih[j * 64 + m] * W_in[m * 32 + c];
        d_Wc[idx] = s;
    }
    if (idx < HID) {
        float s = b_ih[idx] + b_hh[idx];
        #pragma unroll 8
        for (int m = 0; m < 64; m++) s += W_ih[idx * 64 + m] * b_in[m];
        d_bc[idx] = s;
    }
}

// ---------------------------------------------------------------------------
// Kernel C: fused input-projection + sequential RNN scan (R11 layout, single
// 256-step launch — the measured optimum; ~20% above the rt3 FFMA2 floor).
//   h_t = tanh( Wc @ x[:, :, t] + bc  +  W_hh @ h_{t-1} )
// 256 CTAs x 2 batch rows, 128 threads, 2 CTAs/SM. tid = jg*8 + kc.
// Per thread per step: 10 LDS.128, 160 ffma2, 14-shuffle 3-level
// reduce-scatter over the 8 kc lanes. Double-buffered h and x, single
// RAW barrier per step.
// ---------------------------------------------------------------------------
__global__ void __launch_bounds__(128, 2) rnn_kernel(const float* __restrict__ x,
                                                     const float* __restrict__ h0,
                                                     const float* __restrict__ W_hh) {
    __shared__ __align__(16) float hsm[2][2 * 160];      // [buf][row*160 + chunk*20 + off]
    __shared__ __align__(16) float xsm[2][2][16][32];    // [buf][row][tt][c]

    int tid = threadIdx.x;
    int kc = tid & 7;           // 0..7
    int jg = tid >> 3;          // 0..15
    int r0 = blockIdx.x * 2;

    // W_hh slices: 8 j rows x 16 k as pairs (64 ull = 128 regs)
    unsigned long long wp[8][8];
    #pragma unroll
    for (int jj = 0; jj < 8; jj++) {
        const float* wrow = W_hh + (jj * 16 + jg) * 128 + kc * 16;
        #pragma unroll
        for (int i = 0; i < 4; i++) {
            float4 w = *(const float4*)(wrow + i * 4);
            wp[jj][2 * i]     = pack2(w.x, w.y);
            wp[jj][2 * i + 1] = pack2(w.z, w.w);
        }
    }
    // Wc slices: 8 j rows x 4 c as pairs (16 ull = 32 regs)
    unsigned long long wc[8][2];
    #pragma unroll
    for (int jj = 0; jj < 8; jj++) {
        float4 w = *(const float4*)&d_Wc[(jj * 16 + jg) * 32 + kc * 4];
        wc[jj][0] = pack2(w.x, w.y);
        wc[jj][1] = pack2(w.z, w.w);
    }
    int j_out = kc * 16 + jg;
    float bcj = d_bc[j_out];

    // init h state from h0
    for (int i = tid; i < 256; i += 128) {
        int r = i >> 7, k = i & 127;
        hsm[0][r * 160 + (k >> 4) * 20 + (k & 15)] = h0[(r0 + r) * 128 + k];
    }

    // x tile loader: thread (xr, xhalf, xc) loads x[b_r][c][t0+half*8 ..+8)
    int xr = tid >> 6, xhalf = (tid >> 5) & 1, xc = tid & 31;
    const float* xbase = x + ((size_t)(r0 + xr) * 32 + xc) * 256 + xhalf * 8;
    {
        float4 v0 = *(const float4*)(xbase);
        float4 v1 = *(const float4*)(xbase + 4);
        float* xd = &xsm[0][xr][xhalf * 8][xc];
        xd[0 * 32] = v0.x; xd[1 * 32] = v0.y; xd[2 * 32] = v0.z; xd[3 * 32] = v0.w;
        xd[4 * 32] = v1.x; xd[5 * 32] = v1.y; xd[6 * 32] = v1.z; xd[7 * 32] = v1.w;
    }
    __syncthreads();

    float* oA = d_hs + (size_t)r0 * 32768 + j_out;
    float* oB = d_hs + (size_t)(r0 + 1) * 32768 + j_out;

    int hoff = kc * 20;                    // this thread's k-chunk base (words)
    int sst = kc * 20 + jg;                // STS slot (chunk kc, offset jg)

    bool b0 = (kc & 1), b1 = (kc & 2), b2 = (kc & 4);

    for (int t = 0; t < 256; t++) {
        int tt = t & 15;
        int e = t >> 4;

        // prefetch next x epoch (buffer last touched 16 steps ago)
        if (tt == 0 && (t + 16) < 256) {
            int t0 = t + 16;
            float4 v0 = *(const float4*)(xbase + t0);
            float4 v1 = *(const float4*)(xbase + t0 + 4);
            float* xd = &xsm[(e + 1) & 1][xr][xhalf * 8][xc];
            xd[0 * 32] = v0.x; xd[1 * 32] = v0.y; xd[2 * 32] = v0.z; xd[3 * 32] = v0.w;
            xd[4 * 32] = v1.x; xd[5 * 32] = v1.y; xd[6 * 32] = v1.z; xd[7 * 32] = v1.w;
        }

        const float* rbuf = hsm[t & 1];
        float* wbuf = hsm[(t + 1) & 1];

        // ---- per-(row,jj) partials over this thread's 16-k chunk + 4-c proj
        float pr[2][8];
        {
            const ulonglong2* hb = (const ulonglong2*)(rbuf + hoff);
            ulonglong2 hv0 = hb[0], hv1 = hb[1], hv2 = hb[2], hv3 = hb[3];
            ulonglong2 xv = *(const ulonglong2*)&xsm[e & 1][0][tt][kc * 4];
            #pragma unroll
            for (int jj = 0; jj < 8; jj++) {
                unsigned long long a = 0ull;
                ffma2(a, wp[jj][0], hv0.x);
                ffma2(a, wp[jj][1], hv0.y);
                ffma2(a, wp[jj][2], hv1.x);
                ffma2(a, wp[jj][3], hv1.y);
                ffma2(a, wp[jj][4], hv2.x);
                ffma2(a, wp[jj][5], hv2.y);
                ffma2(a, wp[jj][6], hv3.x);
                ffma2(a, wp[jj][7], hv3.y);
                ffma2(a, wc[jj][0], xv.x);
                ffma2(a, wc[jj][1], xv.y);
                float lo, hi; unpack2(a, lo, hi);
                pr[0][jj] = lo + hi;
            }
        }
        {
            const ulonglong2* hb = (const ulonglong2*)(rbuf + 160 + hoff);
            ulonglong2 hv0 = hb[0], hv1 = hb[1], hv2 = hb[2], hv3 = hb[3];
            ulonglong2 xv = *(const ulonglong2*)&xsm[e & 1][1][tt][kc * 4];
            #pragma unroll
            for (int jj = 0; jj < 8; jj++) {
                unsigned long long a = 0ull;
                ffma2(a, wp[jj][0], hv0.x);
                ffma2(a, wp[jj][1], hv0.y);
                ffma2(a, wp[jj][2], hv1.x);
                ffma2(a, wp[jj][3], hv1.y);
                ffma2(a, wp[jj][4], hv2.x);
                ffma2(a, wp[jj][5], hv2.y);
                ffma2(a, wp[jj][6], hv3.x);
                ffma2(a, wp[jj][7], hv3.y);
                ffma2(a, wc[jj][0], xv.x);
                ffma2(a, wc[jj][1], xv.y);
                float lo, hi; unpack2(a, lo, hi);
                pr[1][jj] = lo + hi;
            }
        }

        // ---- 3-level reduce-scatter over the 8 kc lanes ----
        float q[2][4], u[2][2], f[2];
        #pragma unroll
        for (int r = 0; r < 2; r++) {
            #pragma unroll
            for (int m = 0; m < 4; m++)
                q[r][m] = (b0 ? pr[r][2 * m + 1] : pr[r][2 * m])
                        + __shfl_xor_sync(~0u, b0 ? pr[r][2 * m] : pr[r][2 * m + 1], 1);
        }
        #pragma unroll
        for (int r = 0; r < 2; r++) {
            #pragma unroll
            for (int m = 0; m < 2; m++)
                u[r][m] = (b1 ? q[r][2 * m + 1] : q[r][2 * m])
                        + __shfl_xor_sync(~0u, b1 ? q[r][2 * m] : q[r][2 * m + 1], 2);
        }
        #pragma unroll
        for (int r = 0; r < 2; r++)
            f[r] = (b2 ? u[r][1] : u[r][0])
                 + __shfl_xor_sync(~0u, b2 ? u[r][0] : u[r][1], 4);

        float zA = f[0] + bcj;
        float zB = f[1] + bcj;
        float eA = __expf(2.0f * zA);
        float eB = __expf(2.0f * zB);
        float hAv = 1.0f - __fdividef(2.0f, eA + 1.0f);
        float hBv = 1.0f - __fdividef(2.0f, eB + 1.0f);

        wbuf[sst] = hAv;                   // chunk kc, offset jg == j_out slot
        wbuf[160 + sst] = hBv;
        oA[t * 128] = hAv;
        oB[t * 128] = hBv;

        __syncthreads();                   // RAW: h(t) + staged x visible
    }
}

// ---------------------------------------------------------------------------
// Kernel D: bilinear upsample (16->32, align_corners) + hardswish + mean pool.
// smem tile [jj][t], stride 261 -> conflict-free transposed stores and reads.
// ---------------------------------------------------------------------------
__global__ void __launch_bounds__(256) pool_kernel() {
    __shared__ float ht[32 * 261];
    __shared__ float partial[8][32];

    int tid = threadIdx.x;
    int b  = blockIdx.y;
    int j0 = blockIdx.x * 32;

    #pragma unroll
    for (int i = 0; i < 8; i++) {
        int idx4 = i * 256 + tid;
        int t = idx4 >> 3, q = idx4 & 7;
        float4 v = *(const float4*)&d_hs[((size_t)b * 256 + t) * 128 + j0 + q * 4];
        ht[(q * 4 + 0) * 261 + t] = v.x;
        ht[(q * 4 + 1) * 261 + t] = v.y;
        ht[(q * 4 + 2) * 261 + t] = v.z;
        ht[(q * 4 + 3) * 261 + t] = v.w;
    }
    __syncthreads();

    int jj = tid & 31, p = tid >> 5;
    const float* hrow = ht + jj * 261;
    float acc = 0.f;

    #pragma unroll
    for (int q = 0; q < 4; q++) {
        int oy = p * 4 + q;
        float ysf = (float)(oy * 15) / 31.0f;
        int y0 = (int)ysf;
        float wy = ysf - (float)y0;
        int y1 = min(y0 + 1, 15);

        const float* pa = hrow + y0 * 16;
        const float* pb = hrow + y1 * 16;
        float rv[16];
        #pragma unroll
        for (int xq = 0; xq < 16; xq++) {
            float a = pa[xq], c = pb[xq];
            rv[xq] = fmaf(c - a, wy, a);
        }

        #pragma unroll
        for (int ox = 0; ox < 32; ox++) {
            const int x0 = (ox * 15) / 31;
            const int x1 = (x0 + 1 < 16) ? (x0 + 1) : 15;
            const float wx = (float)(ox * 15) / 31.0f - (float)x0;
            float v = fmaf(rv[x1] - rv[x0], wx, rv[x0]);
            acc = fmaf(v, fminf(fmaxf(v + 3.0f, 0.0f), 6.0f), acc);
        }
    }

    partial[p][jj] = acc;
    __syncthreads();
    if (p == 0) {
        float s = 0.f;
        #pragma unroll
        for (int q = 0; q < 8; q++) s += partial[q][jj];
        d_pooled[b * 128 + j0 + jj] = s * (1.0f / (6.0f * 1024.0f));
    }
}

// ---------------------------------------------------------------------------
// Kernel E: out[b][o] = b_out[o] + sum_j pooled[b][j] * W_out[o][j]
// 32x32 tiles -> grid (16,16) = 256 CTAs (~2/SM vs 0.43 before). 256 threads,
// 2x2 microtile, single k=128 pass (one barrier). smem pad 129 keeps the
// row-pair reads conflict-free (16 distinct rows -> 16 banks, 2-thread
// broadcast per row).
// ---------------------------------------------------------------------------
__global__ void __launch_bounds__(256) out_gemm(const float* __restrict__ W_out,
                                                const float* __restrict__ b_out,
                                                float* __restrict__ out) {
    __shared__ float ws[32][129];
    __shared__ float ps[32][129];

    int tid = threadIdx.x;
    int o0 = blockIdx.x * 32, b0 = blockIdx.y * 32;

    // load both 32x128 tiles (1024 float4 each; 4 per thread per tile)
    #pragma unroll
    for (int i = 0; i < 4; i++) {
        int idx4 = i * 256 + tid;
        int r = idx4 >> 5, c4 = idx4 & 31;
        float4 w = *(const float4*)&W_out[(o0 + r) * 128 + c4 * 4];
        ws[r][c4 * 4 + 0] = w.x; ws[r][c4 * 4 + 1] = w.y;
        ws[r][c4 * 4 + 2] = w.z; ws[r][c4 * 4 + 3] = w.w;
        float4 p = *(const float4*)&d_pooled[(b0 + r) * 128 + c4 * 4];
        ps[r][c4 * 4 + 0] = p.x; ps[r][c4 * 4 + 1] = p.y;
        ps[r][c4 * 4 + 2] = p.z; ps[r][c4 * 4 + 3] = p.w;
    }
    __syncthreads();

    int to = (tid & 15) * 2;
    int tb = (tid >> 4) * 2;

    float acc[2][2] = {};
    #pragma unroll 8
    for (int k = 0; k < 128; k++) {
        float w0 = ws[to][k], w1 = ws[to + 1][k];
        float p0 = ps[tb][k], p1 = ps[tb + 1][k];
        acc[0][0] = fmaf(p0, w0, acc[0][0]);
        acc[0][1] = fmaf(p0, w1, acc[0][1]);
        acc[1][0] = fmaf(p1, w0, acc[1][0]);
        acc[1][1] = fmaf(p1, w1, acc[1][1]);
    }

    #pragma unroll
    for (int mb = 0; mb < 2; mb++)
        #pragma unroll
        for (int mo = 0; mo < 2; mo++)
            out[(b0 + tb + mb) * 512 + o0 + to + mo] = acc[mb][mo] + b_out[o0 + to + mo];
}

// ---------------------------------------------------------------------------
extern "C" void kernel_launch(void* const* d_in, const int* in_sizes, int n_in,
                              void* d_out, int out_size) {
    const float* x     = (const float*)d_in[0];
    const float* h0    = (const float*)d_in[1];
    const float* W_in  = (const float*)d_in[2];
    const float* b_in  = (const float*)d_in[3];
    const float* W_ih  = (const float*)d_in[4];
    const float* b_ih  = (const float*)d_in[5];
    const float* W_hh  = (const float*)d_in[6];
    const float* b_hh  = (const float*)d_in[7];
    const float* W_out = (const float*)d_in[8];
    const float* b_out = (const float*)d_in[9];
    float* out = (float*)d_out;

    combine_kernel<<<16, 256>>>(W_in, b_in, W_ih, b_ih, b_hh);
    rnn_kernel<<<256, 128>>>(x, h0, W_hh);
    pool_kernel<<<dim3(4, 512), 256>>>();
    out_gemm<<<dim3(16, 16), 256>>>(W_out, b_out, out);
}